// round 4
// baseline (speedup 1.0000x reference)
#include <cuda_runtime.h>
#include <stdint.h>

#define N_NODES 50000
#define N_EDGES 200000
#define HID 32
#define YROW 1056   // 33 * 32: rows k=0..31 are w2 image, row 32 is b2 image

// ---------------- device scratch (static allocation only) ----------------
__device__ int   g_is64;
__device__ int   g_src[N_EDGES], g_dst[N_EDGES];
__device__ float g_hA[N_NODES * HID];
__device__ float g_hB[N_NODES * HID];
__device__ float g_Y[(size_t)N_NODES * YROW];   // ~211 MB
__device__ float g_agg[N_NODES * HID];
__device__ float g_cnt[N_NODES];

// ---------------- edge_index dtype detection ----------------
// int64 (little-endian): every odd 32-bit word is a high word == 0 (values
// < 50000). int32: odd words are src[1],src[3],... — random, not all zero.
__global__ __launch_bounds__(256) void detect_kernel(const void* ei) {
    const unsigned* u = (const unsigned*)ei;
    __shared__ int any;
    if (threadIdx.x == 0) any = 0;
    __syncthreads();
    int local = 0;
    for (int i = threadIdx.x; i < 8192; i += blockDim.x)
        if (u[2 * i + 1] != 0u) local = 1;
    if (local) atomicOr(&any, 1);
    __syncthreads();
    if (threadIdx.x == 0) g_is64 = (any == 0) ? 1 : 0;
}

__global__ __launch_bounds__(256) void normalize_edges(const void* ei) {
    int e = blockIdx.x * blockDim.x + threadIdx.x;
    if (e >= N_EDGES) return;
    int s, d;
    if (g_is64) {
        const long long* p = (const long long*)ei;
        s = (int)p[e];
        d = (int)p[N_EDGES + e];
    } else {
        const int* p = (const int*)ei;
        s = p[e];
        d = p[N_EDGES + e];
    }
    s = min(max(s, 0), N_NODES - 1);
    d = min(max(d, 0), N_NODES - 1);
    g_src[e] = s;
    g_dst[e] = d;
}

// ---------------- h0 = relu(x @ Win + b), x:[N,64] Win:[64,32] --------------
__global__ __launch_bounds__(256) void inproj_kernel(
    const float* __restrict__ x, const float* __restrict__ W,
    const float* __restrict__ b, float* __restrict__ hout) {
    __shared__ float sW[64 * 32];
    __shared__ float sb[32];
    int tid = threadIdx.x;
    for (int i = tid; i < 64 * 32; i += 256) sW[i] = W[i];
    if (tid < 32) sb[tid] = b[tid];
    __syncthreads();
    int lane = tid & 31, wid = tid >> 5;
    int n = blockIdx.x * 8 + wid;
    if (n >= N_NODES) return;
    float xa = x[n * 64 + lane];
    float xb = x[n * 64 + 32 + lane];
    float r = sb[lane];
#pragma unroll
    for (int k = 0; k < 32; k++)
        r = fmaf(__shfl_sync(0xffffffffu, xa, k), sW[k * 32 + lane], r);
#pragma unroll
    for (int k = 0; k < 32; k++)
        r = fmaf(__shfl_sync(0xffffffffu, xb, k), sW[(k + 32) * 32 + lane], r);
    hout[n * 32 + lane] = fmaxf(r, 0.f);
}

// ---------------- Y precompute ---------------------------------------------
// Y[n][k][o] = sum_h h[n][h] * w2[k][h*32+o]   (k<32)
// Y[n][32][o] = sum_h h[n][h] * b2[h*32+o]     (bias image; b2 indexed h*32+o)
// Block: 32 nodes. Warp w owns nodes w*4..w*4+3 (one h value per lane each).
__global__ __launch_bounds__(256) void y_kernel(
    const float* __restrict__ h, const float* __restrict__ w2,
    const float* __restrict__ b2, float* __restrict__ Y) {
    __shared__ float sh[32 * 32];
    __shared__ float sw[1024];
    int tid = threadIdx.x, lane = tid & 31, wid = tid >> 5;
    int n0 = blockIdx.x * 32;

    for (int i = tid; i < 1024; i += 256) {
        int s = i >> 5, c = i & 31;
        int n = n0 + s;
        sh[i] = (n < N_NODES) ? h[n * 32 + c] : 0.f;
    }
    __syncthreads();

    int nb = wid * 4;
    float hv0 = sh[(nb + 0) * 32 + lane];
    float hv1 = sh[(nb + 1) * 32 + lane];
    float hv2 = sh[(nb + 2) * 32 + lane];
    float hv3 = sh[(nb + 3) * 32 + lane];

    for (int k = 0; k < 33; k++) {
        const float* row = (k < 32) ? (w2 + k * 1024) : b2;
        __syncthreads();
        *reinterpret_cast<float4*>(sw + tid * 4) =
            *reinterpret_cast<const float4*>(row + tid * 4);
        __syncthreads();
        float a0 = 0.f, a1 = 0.f, a2 = 0.f, a3 = 0.f;
#pragma unroll
        for (int hh = 0; hh < 32; hh++) {
            float w = sw[hh * 32 + lane];
            a0 = fmaf(__shfl_sync(0xffffffffu, hv0, hh), w, a0);
            a1 = fmaf(__shfl_sync(0xffffffffu, hv1, hh), w, a1);
            a2 = fmaf(__shfl_sync(0xffffffffu, hv2, hh), w, a2);
            a3 = fmaf(__shfl_sync(0xffffffffu, hv3, hh), w, a3);
        }
        size_t base = (size_t)(n0 + nb) * YROW + k * 32 + lane;
        if (n0 + nb + 0 < N_NODES) Y[base + 0 * YROW] = a0;
        if (n0 + nb + 1 < N_NODES) Y[base + 1 * YROW] = a1;
        if (n0 + nb + 2 < N_NODES) Y[base + 2 * YROW] = a2;
        if (n0 + nb + 3 < N_NODES) Y[base + 3 * YROW] = a3;
    }
}

// ---------------- edge kernel: warp per edge, atomic scatter ----------------
// he = relu(ea @ w1 + b1);  msg[o] = Y[s][32][o] + sum_k he[k]*Y[s][k][o]
__global__ __launch_bounds__(256) void edge_kernel(
    const float* __restrict__ ea, const float* __restrict__ w1,
    const float* __restrict__ b1, const float* __restrict__ Y,
    float* __restrict__ agg, float* __restrict__ cnt) {
    __shared__ float sw1[16 * 32];
    __shared__ float sb1[32];
    int tid = threadIdx.x, lane = tid & 31, wid = tid >> 5;
    for (int i = tid; i < 512; i += 256) sw1[i] = w1[i];
    if (tid < 32) sb1[tid] = b1[tid];
    __syncthreads();

    int e = blockIdx.x * 8 + wid;
    if (e >= N_EDGES) return;
    int s = g_src[e];
    int d = g_dst[e];

    const float* eap = ea + (size_t)e * 16;
    float acc = sb1[lane];
#pragma unroll
    for (int j = 0; j < 16; j++)
        acc = fmaf(__ldg(eap + j), sw1[j * 32 + lane], acc);
    float he = fmaxf(acc, 0.f);

    const float* yb = Y + (size_t)s * YROW + lane;
    float m = yb[32 * 32];  // bias image row
#pragma unroll
    for (int k = 0; k < 32; k++)
        m = fmaf(__shfl_sync(0xffffffffu, he, k), yb[k * 32], m);

    atomicAdd(&agg[(size_t)d * 32 + lane], m);
    if (lane == 0) atomicAdd(&cnt[d], 1.f);
}

// ---------------- node update: h' = relu(agg/cnt + h@rootW + rootb) ---------
__global__ __launch_bounds__(256) void node_update_kernel(
    const float* __restrict__ hin, const float* __restrict__ agg,
    const float* __restrict__ cnt, const float* __restrict__ rW,
    const float* __restrict__ rb, float* __restrict__ hout) {
    __shared__ float sW[32 * 32];
    __shared__ float sb[32];
    int tid = threadIdx.x;
    for (int i = tid; i < 1024; i += 256) sW[i] = rW[i];
    if (tid < 32) sb[tid] = rb[tid];
    __syncthreads();
    int lane = tid & 31, wid = tid >> 5;
    int n = blockIdx.x * 8 + wid;
    if (n >= N_NODES) return;
    float a = agg[n * 32 + lane] / fmaxf(cnt[n], 1.f);
    float hv = hin[n * 32 + lane];
    float r = sb[lane] + a;
#pragma unroll
    for (int k = 0; k < 32; k++)
        r = fmaf(__shfl_sync(0xffffffffu, hv, k), sW[k * 32 + lane], r);
    hout[n * 32 + lane] = fmaxf(r, 0.f);
}

// ---------------- fused head: z=h@Wo+bo; d1=relu(z@W1+b1); out=d1@W2+b2 -----
__global__ __launch_bounds__(256) void decoder_kernel(
    const float* __restrict__ h, const float* __restrict__ Wo,
    const float* __restrict__ bo, const float* __restrict__ W1,
    const float* __restrict__ b1, const float* __restrict__ W2,
    const float* __restrict__ b2, float* __restrict__ out) {
    __shared__ float sWo[32 * 16], sW1[16 * 32], sW2[32 * 64];
    __shared__ float sbo[16], sb1[32], sb2[64];
    int tid = threadIdx.x;
    for (int i = tid; i < 512; i += 256) { sWo[i] = Wo[i]; sW1[i] = W1[i]; }
    for (int i = tid; i < 2048; i += 256) sW2[i] = W2[i];
    if (tid < 16) sbo[tid] = bo[tid];
    if (tid < 32) sb1[tid] = b1[tid];
    if (tid < 64) sb2[tid] = b2[tid];
    __syncthreads();
    int lane = tid & 31, wid = tid >> 5;
    int n = blockIdx.x * 8 + wid;
    if (n >= N_NODES) return;
    float hv = h[n * 32 + lane];
    int l16 = lane & 15;
    float z = sbo[l16];
#pragma unroll
    for (int k = 0; k < 32; k++)
        z = fmaf(__shfl_sync(0xffffffffu, hv, k), sWo[k * 16 + l16], z);
    float d1 = sb1[lane];
#pragma unroll
    for (int j = 0; j < 16; j++)
        d1 = fmaf(__shfl_sync(0xffffffffu, z, j), sW1[j * 32 + lane], d1);
    d1 = fmaxf(d1, 0.f);
    float o0 = sb2[lane], o1 = sb2[32 + lane];
#pragma unroll
    for (int j = 0; j < 32; j++) {
        float dj = __shfl_sync(0xffffffffu, d1, j);
        o0 = fmaf(dj, sW2[j * 64 + lane], o0);
        o1 = fmaf(dj, sW2[j * 64 + 32 + lane], o1);
    }
    out[n * 64 + lane] = o0;
    out[n * 64 + 32 + lane] = o1;
}

// ---------------- launch ----------------
extern "C" void kernel_launch(void* const* d_in, const int* in_sizes, int n_in,
                              void* d_out, int out_size) {
    const float* x        = (const float*)d_in[0];
    const void*  ei       = d_in[1];
    const float* ea       = (const float*)d_in[2];
    const float* lin_in_w = (const float*)d_in[3];
    const float* lin_in_b = (const float*)d_in[4];
    const float* edge_w1  = (const float*)d_in[5];
    const float* edge_b1  = (const float*)d_in[6];
    const float* edge_w2  = (const float*)d_in[7];
    const float* edge_b2  = (const float*)d_in[8];
    const float* root_w   = (const float*)d_in[9];
    const float* root_b   = (const float*)d_in[10];
    const float* lout_w   = (const float*)d_in[11];
    const float* lout_b   = (const float*)d_in[12];
    const float* dec_w1   = (const float*)d_in[13];
    const float* dec_b1   = (const float*)d_in[14];
    const float* dec_w2   = (const float*)d_in[15];
    const float* dec_b2   = (const float*)d_in[16];
    float* out = (float*)d_out;

    void *p_agg, *p_cnt, *p_Y, *p_hA, *p_hB;
    cudaGetSymbolAddress(&p_agg, g_agg);
    cudaGetSymbolAddress(&p_cnt, g_cnt);
    cudaGetSymbolAddress(&p_Y, g_Y);
    cudaGetSymbolAddress(&p_hA, g_hA);
    cudaGetSymbolAddress(&p_hB, g_hB);
    float* hbuf[4] = {(float*)p_hA, (float*)p_hB, (float*)p_hA, (float*)p_hB};

    const int EB = (N_EDGES + 255) / 256;
    detect_kernel<<<1, 256>>>(ei);
    normalize_edges<<<EB, 256>>>(ei);

    const int NB = (N_NODES + 7) / 8;
    inproj_kernel<<<NB, 256>>>(x, lin_in_w, lin_in_b, (float*)p_hA);

    const int YB = (N_NODES + 31) / 32;
    const int EGB = (N_EDGES + 7) / 8;
    for (int L = 0; L < 3; L++) {
        const float* w1 = edge_w1 + L * 16 * 32;
        const float* b1 = edge_b1 + L * 32;
        const float* w2 = edge_w2 + L * 32 * 1024;
        const float* b2 = edge_b2 + L * 1024;
        const float* rw = root_w + L * 32 * 32;
        const float* rb = root_b + L * 32;
        const float* hin = hbuf[L];
        float* hout = hbuf[L + 1];

        y_kernel<<<YB, 256>>>(hin, w2, b2, (float*)p_Y);
        cudaMemsetAsync(p_agg, 0, (size_t)N_NODES * HID * sizeof(float), 0);
        cudaMemsetAsync(p_cnt, 0, (size_t)N_NODES * sizeof(float), 0);
        edge_kernel<<<EGB, 256>>>(ea, w1, b1, (const float*)p_Y,
                                  (float*)p_agg, (float*)p_cnt);
        node_update_kernel<<<NB, 256>>>(hin, (const float*)p_agg,
                                        (const float*)p_cnt, rw, rb, hout);
    }
    decoder_kernel<<<NB, 256>>>(hbuf[3], lout_w, lout_b, dec_w1, dec_b1,
                                dec_w2, dec_b2, out);
}

// round 5
// speedup vs baseline: 1.0768x; 1.0768x over previous
#include <cuda_runtime.h>
#include <cuda_bf16.h>
#include <stdint.h>

#define N_NODES 50000
#define N_EDGES 200000
#define HID 32

// ---------------- device scratch (static allocation only) ----------------
__device__ int      g_is64;
__device__ int      g_src[N_EDGES], g_dst[N_EDGES];
__device__ float    g_hA[N_NODES * HID];
__device__ float    g_hB[N_NODES * HID];
__device__ float    g_w2t[33 * 1024];                 // [k][o][h] transposed w2 (+b2 image at k=32)
__device__ unsigned g_Yt[(size_t)N_NODES * 512];      // bf16x2 packed, [n][o][k/2]  (~102 MB)
__device__ float    g_Yb[N_NODES * HID];              // bias image row (fp32)
__device__ float    g_agg[N_NODES * HID];
__device__ float    g_cnt[N_NODES];

// ---------------- edge_index dtype detection ----------------
__global__ __launch_bounds__(256) void detect_kernel(const void* ei) {
    const unsigned* u = (const unsigned*)ei;
    __shared__ int any;
    if (threadIdx.x == 0) any = 0;
    __syncthreads();
    int local = 0;
    for (int i = threadIdx.x; i < 8192; i += blockDim.x)
        if (u[2 * i + 1] != 0u) local = 1;
    if (local) atomicOr(&any, 1);
    __syncthreads();
    if (threadIdx.x == 0) g_is64 = (any == 0) ? 1 : 0;
}

__global__ __launch_bounds__(256) void normalize_edges(const void* ei) {
    int e = blockIdx.x * blockDim.x + threadIdx.x;
    if (e >= N_EDGES) return;
    int s, d;
    if (g_is64) {
        const long long* p = (const long long*)ei;
        s = (int)p[e];
        d = (int)p[N_EDGES + e];
    } else {
        const int* p = (const int*)ei;
        s = p[e];
        d = p[N_EDGES + e];
    }
    s = min(max(s, 0), N_NODES - 1);
    d = min(max(d, 0), N_NODES - 1);
    g_src[e] = s;
    g_dst[e] = d;
}

// degree counts (layer-invariant, computed once)
__global__ __launch_bounds__(256) void count_dst_kernel() {
    int e = blockIdx.x * blockDim.x + threadIdx.x;
    if (e >= N_EDGES) return;
    atomicAdd(&g_cnt[g_dst[e]], 1.f);
}

// ---------------- h0 = relu(x @ Win + b) ------------------------------------
__global__ __launch_bounds__(256) void inproj_kernel(
    const float* __restrict__ x, const float* __restrict__ W,
    const float* __restrict__ b, float* __restrict__ hout) {
    __shared__ float sW[64 * 32];
    __shared__ float sb[32];
    int tid = threadIdx.x;
    for (int i = tid; i < 64 * 32; i += 256) sW[i] = W[i];
    if (tid < 32) sb[tid] = b[tid];
    __syncthreads();
    int lane = tid & 31, wid = tid >> 5;
    int n = blockIdx.x * 8 + wid;
    if (n >= N_NODES) return;
    float xa = x[n * 64 + lane];
    float xb = x[n * 64 + 32 + lane];
    float r = sb[lane];
#pragma unroll
    for (int k = 0; k < 32; k++)
        r = fmaf(__shfl_sync(0xffffffffu, xa, k), sW[k * 32 + lane], r);
#pragma unroll
    for (int k = 0; k < 32; k++)
        r = fmaf(__shfl_sync(0xffffffffu, xb, k), sW[(k + 32) * 32 + lane], r);
    hout[n * 32 + lane] = fmaxf(r, 0.f);
}

// ---------------- w2 transpose: g_w2t[k][o][h] = w2[k][h*32+o] --------------
__global__ __launch_bounds__(256) void w2t_kernel(
    const float* __restrict__ w2, const float* __restrict__ b2) {
    int k = blockIdx.x;  // 0..32
    const float* row = (k < 32) ? (w2 + k * 1024) : b2;
    int t = threadIdx.x;
    int o = t >> 3, hb = (t & 7) * 4;
    float4 v;
    v.x = row[(hb + 0) * 32 + o];
    v.y = row[(hb + 1) * 32 + o];
    v.z = row[(hb + 2) * 32 + o];
    v.w = row[(hb + 3) * 32 + o];
    *reinterpret_cast<float4*>(g_w2t + k * 1024 + o * 32 + hb) = v;
}

// ---------------- Y precompute (warp = node, no shuffles) -------------------
// fk[k] = sum_h h[n][h] * w2t[k][lane][h];  packed bf16x2 out + fp32 bias row.
__global__ __launch_bounds__(256) void y_kernel(const float* __restrict__ h) {
    __shared__ float swt[32 * 36];   // [o][h] padded
    int tid = threadIdx.x, lane = tid & 31, wid = tid >> 5;
    int n = blockIdx.x * 8 + wid;

    float4 hr[8];
    if (n < N_NODES) {
        const float4* hp = reinterpret_cast<const float4*>(h + (size_t)n * 32);
#pragma unroll
        for (int i = 0; i < 8; i++) hr[i] = __ldg(hp + i);
    } else {
#pragma unroll
        for (int i = 0; i < 8; i++) hr[i] = make_float4(0.f, 0.f, 0.f, 0.f);
    }

    int so = (tid >> 3) * 36 + (tid & 7) * 4;  // staging dest: o*36 + hb
    float fk[33];
#pragma unroll
    for (int k = 0; k < 33; k++) {
        __syncthreads();
        *reinterpret_cast<float4*>(swt + so) =
            *reinterpret_cast<const float4*>(g_w2t + k * 1024 + tid * 4);
        __syncthreads();
        float a0 = 0.f, a1 = 0.f, a2 = 0.f, a3 = 0.f;
        const float* wr = swt + lane * 36;
#pragma unroll
        for (int i = 0; i < 8; i++) {
            float4 wv = *reinterpret_cast<const float4*>(wr + i * 4);
            float4 hv = hr[i];
            a0 = fmaf(hv.x, wv.x, a0);
            a1 = fmaf(hv.y, wv.y, a1);
            a2 = fmaf(hv.z, wv.z, a2);
            a3 = fmaf(hv.w, wv.w, a3);
        }
        fk[k] = (a0 + a1) + (a2 + a3);
    }

    if (n < N_NODES) {
        unsigned u[16];
#pragma unroll
        for (int j = 0; j < 16; j++) {
            __nv_bfloat162 p = __floats2bfloat162_rn(fk[2 * j], fk[2 * j + 1]);
            u[j] = *reinterpret_cast<unsigned*>(&p);
        }
        uint4* yp = reinterpret_cast<uint4*>(g_Yt) + (size_t)n * 128 + lane * 4;
        yp[0] = make_uint4(u[0], u[1], u[2], u[3]);
        yp[1] = make_uint4(u[4], u[5], u[6], u[7]);
        yp[2] = make_uint4(u[8], u[9], u[10], u[11]);
        yp[3] = make_uint4(u[12], u[13], u[14], u[15]);
        g_Yb[n * 32 + lane] = fk[32];
    }
}

// ---------------- edge kernel: warp per edge, bf16 Y gather -----------------
__global__ __launch_bounds__(256) void edge_kernel(
    const float* __restrict__ ea, const float* __restrict__ w1,
    const float* __restrict__ b1, float* __restrict__ agg) {
    __shared__ float sw1[16 * 32];
    __shared__ float sb1[32];
    int tid = threadIdx.x, lane = tid & 31, wid = tid >> 5;
    for (int i = tid; i < 512; i += 256) sw1[i] = w1[i];
    if (tid < 32) sb1[tid] = b1[tid];
    __syncthreads();

    int e = blockIdx.x * 8 + wid;
    if (e >= N_EDGES) return;
    int s = g_src[e];
    int d = g_dst[e];

    const float4* eap = reinterpret_cast<const float4*>(ea + (size_t)e * 16);
    float acc = sb1[lane];
#pragma unroll
    for (int j = 0; j < 4; j++) {
        float4 av = __ldg(eap + j);
        acc = fmaf(av.x, sw1[(4 * j + 0) * 32 + lane], acc);
        acc = fmaf(av.y, sw1[(4 * j + 1) * 32 + lane], acc);
        acc = fmaf(av.z, sw1[(4 * j + 2) * 32 + lane], acc);
        acc = fmaf(av.w, sw1[(4 * j + 3) * 32 + lane], acc);
    }
    float he = fmaxf(acc, 0.f);

    float m0 = __ldg(g_Yb + (size_t)s * 32 + lane);
    float m1 = 0.f;
    const uint4* yp = reinterpret_cast<const uint4*>(g_Yt) + (size_t)s * 128 + lane * 4;
#pragma unroll
    for (int i = 0; i < 4; i++) {
        uint4 q = __ldg(yp + i);
        unsigned uu[4] = {q.x, q.y, q.z, q.w};
#pragma unroll
        for (int c = 0; c < 4; c++) {
            int k = i * 8 + c * 2;
            float lo = __int_as_float(uu[c] << 16);
            float hi = __int_as_float(uu[c] & 0xffff0000u);
            m0 = fmaf(__shfl_sync(0xffffffffu, he, k), lo, m0);
            m1 = fmaf(__shfl_sync(0xffffffffu, he, k + 1), hi, m1);
        }
    }
    atomicAdd(&agg[(size_t)d * 32 + lane], m0 + m1);
}

// ---------------- node update: h' = relu(agg/cnt + h@rootW + rootb) ---------
__global__ __launch_bounds__(256) void node_update_kernel(
    const float* __restrict__ hin, const float* __restrict__ agg,
    const float* __restrict__ cnt, const float* __restrict__ rW,
    const float* __restrict__ rb, float* __restrict__ hout) {
    __shared__ float sW[32 * 32];
    __shared__ float sb[32];
    int tid = threadIdx.x;
    for (int i = tid; i < 1024; i += 256) sW[i] = rW[i];
    if (tid < 32) sb[tid] = rb[tid];
    __syncthreads();
    int lane = tid & 31, wid = tid >> 5;
    int n = blockIdx.x * 8 + wid;
    if (n >= N_NODES) return;
    float a = agg[n * 32 + lane] / fmaxf(cnt[n], 1.f);
    float hv = hin[n * 32 + lane];
    float r = sb[lane] + a;
#pragma unroll
    for (int k = 0; k < 32; k++)
        r = fmaf(__shfl_sync(0xffffffffu, hv, k), sW[k * 32 + lane], r);
    hout[n * 32 + lane] = fmaxf(r, 0.f);
}

// ---------------- fused head: z=h@Wo+bo; d1=relu(z@W1+b1); out=d1@W2+b2 -----
__global__ __launch_bounds__(256) void decoder_kernel(
    const float* __restrict__ h, const float* __restrict__ Wo,
    const float* __restrict__ bo, const float* __restrict__ W1,
    const float* __restrict__ b1, const float* __restrict__ W2,
    const float* __restrict__ b2, float* __restrict__ out) {
    __shared__ float sWo[32 * 16], sW1[16 * 32], sW2[32 * 64];
    __shared__ float sbo[16], sb1[32], sb2[64];
    int tid = threadIdx.x;
    for (int i = tid; i < 512; i += 256) { sWo[i] = Wo[i]; sW1[i] = W1[i]; }
    for (int i = tid; i < 2048; i += 256) sW2[i] = W2[i];
    if (tid < 16) sbo[tid] = bo[tid];
    if (tid < 32) sb1[tid] = b1[tid];
    if (tid < 64) sb2[tid] = b2[tid];
    __syncthreads();
    int lane = tid & 31, wid = tid >> 5;
    int n = blockIdx.x * 8 + wid;
    if (n >= N_NODES) return;
    float hv = h[n * 32 + lane];
    int l16 = lane & 15;
    float z = sbo[l16];
#pragma unroll
    for (int k = 0; k < 32; k++)
        z = fmaf(__shfl_sync(0xffffffffu, hv, k), sWo[k * 16 + l16], z);
    float d1 = sb1[lane];
#pragma unroll
    for (int j = 0; j < 16; j++)
        d1 = fmaf(__shfl_sync(0xffffffffu, z, j), sW1[j * 32 + lane], d1);
    d1 = fmaxf(d1, 0.f);
    float o0 = sb2[lane], o1 = sb2[32 + lane];
#pragma unroll
    for (int j = 0; j < 32; j++) {
        float dj = __shfl_sync(0xffffffffu, d1, j);
        o0 = fmaf(dj, sW2[j * 64 + lane], o0);
        o1 = fmaf(dj, sW2[j * 64 + 32 + lane], o1);
    }
    out[n * 64 + lane] = o0;
    out[n * 64 + 32 + lane] = o1;
}

// ---------------- launch ----------------
extern "C" void kernel_launch(void* const* d_in, const int* in_sizes, int n_in,
                              void* d_out, int out_size) {
    const float* x        = (const float*)d_in[0];
    const void*  ei       = d_in[1];
    const float* ea       = (const float*)d_in[2];
    const float* lin_in_w = (const float*)d_in[3];
    const float* lin_in_b = (const float*)d_in[4];
    const float* edge_w1  = (const float*)d_in[5];
    const float* edge_b1  = (const float*)d_in[6];
    const float* edge_w2  = (const float*)d_in[7];
    const float* edge_b2  = (const float*)d_in[8];
    const float* root_w   = (const float*)d_in[9];
    const float* root_b   = (const float*)d_in[10];
    const float* lout_w   = (const float*)d_in[11];
    const float* lout_b   = (const float*)d_in[12];
    const float* dec_w1   = (const float*)d_in[13];
    const float* dec_b1   = (const float*)d_in[14];
    const float* dec_w2   = (const float*)d_in[15];
    const float* dec_b2   = (const float*)d_in[16];
    float* out = (float*)d_out;

    void *p_agg, *p_cnt, *p_hA, *p_hB;
    cudaGetSymbolAddress(&p_agg, g_agg);
    cudaGetSymbolAddress(&p_cnt, g_cnt);
    cudaGetSymbolAddress(&p_hA, g_hA);
    cudaGetSymbolAddress(&p_hB, g_hB);
    float* hbuf[4] = {(float*)p_hA, (float*)p_hB, (float*)p_hA, (float*)p_hB};

    const int EB = (N_EDGES + 255) / 256;
    detect_kernel<<<1, 256>>>(ei);
    normalize_edges<<<EB, 256>>>(ei);
    cudaMemsetAsync(p_cnt, 0, (size_t)N_NODES * sizeof(float), 0);
    count_dst_kernel<<<EB, 256>>>();

    const int NB = (N_NODES + 7) / 8;
    inproj_kernel<<<NB, 256>>>(x, lin_in_w, lin_in_b, (float*)p_hA);

    const int YB = (N_NODES + 7) / 8;
    const int EGB = (N_EDGES + 7) / 8;
    for (int L = 0; L < 3; L++) {
        const float* w1 = edge_w1 + L * 16 * 32;
        const float* b1 = edge_b1 + L * 32;
        const float* w2 = edge_w2 + L * 32 * 1024;
        const float* b2 = edge_b2 + L * 1024;
        const float* rw = root_w + L * 32 * 32;
        const float* rb = root_b + L * 32;
        const float* hin = hbuf[L];
        float* hout = hbuf[L + 1];

        w2t_kernel<<<33, 256>>>(w2, b2);
        y_kernel<<<YB, 256>>>(hin);
        cudaMemsetAsync(p_agg, 0, (size_t)N_NODES * HID * sizeof(float), 0);
        edge_kernel<<<EGB, 256>>>(ea, w1, b1, (float*)p_agg);
        node_update_kernel<<<NB, 256>>>(hin, (const float*)p_agg,
                                        (const float*)p_cnt, rw, rb, hout);
    }
    decoder_kernel<<<NB, 256>>>(hbuf[3], lout_w, lout_b, dec_w1, dec_b1,
                                dec_w2, dec_b2, out);
}

// round 8
// speedup vs baseline: 2.1585x; 2.0047x over previous
#include <cuda_runtime.h>
#include <cuda_bf16.h>
#include <stdint.h>

#define N_NODES 50000
#define N_EDGES 200000
#define HID 32
#define M_TILES 391          // ceil(50000/128)

// ---------------- device scratch (static allocation only) ----------------
__device__ int            g_is64;
__device__ int            g_src[N_EDGES], g_dst[N_EDGES];
__device__ float          g_hA[N_NODES * HID];
__device__ float          g_hB[N_NODES * HID];
__device__ unsigned short g_w2tb[1056 * 32];           // bf16 [col][h]; col=o*32+k, 1024+o=bias
__device__ unsigned       g_Yt[(size_t)N_NODES * 512]; // bf16x2 packed [n][o][k/2]
__device__ float          g_Yb[N_NODES * HID];         // bias image row (fp32)
__device__ float          g_agg[N_NODES * HID];
__device__ float          g_cnt[N_NODES];

// ---------------- edge_index dtype detection ----------------
__global__ __launch_bounds__(256) void detect_kernel(const void* ei) {
    const unsigned* u = (const unsigned*)ei;
    __shared__ int any;
    if (threadIdx.x == 0) any = 0;
    __syncthreads();
    int local = 0;
    for (int i = threadIdx.x; i < 8192; i += blockDim.x)
        if (u[2 * i + 1] != 0u) local = 1;
    if (local) atomicOr(&any, 1);
    __syncthreads();
    if (threadIdx.x == 0) g_is64 = (any == 0) ? 1 : 0;
}

__global__ __launch_bounds__(256) void normalize_edges(const void* ei) {
    int e = blockIdx.x * blockDim.x + threadIdx.x;
    if (e >= N_EDGES) return;
    int s, d;
    if (g_is64) {
        const long long* p = (const long long*)ei;
        s = (int)p[e];
        d = (int)p[N_EDGES + e];
    } else {
        const int* p = (const int*)ei;
        s = p[e];
        d = p[N_EDGES + e];
    }
    s = min(max(s, 0), N_NODES - 1);
    d = min(max(d, 0), N_NODES - 1);
    g_src[e] = s;
    g_dst[e] = d;
}

__global__ __launch_bounds__(256) void count_dst_kernel() {
    int e = blockIdx.x * blockDim.x + threadIdx.x;
    if (e >= N_EDGES) return;
    atomicAdd(&g_cnt[g_dst[e]], 1.f);
}

// ---------------- h0 = relu(x @ Win + b) ------------------------------------
__global__ __launch_bounds__(256) void inproj_kernel(
    const float* __restrict__ x, const float* __restrict__ W,
    const float* __restrict__ b, float* __restrict__ hout) {
    __shared__ float sW[64 * 32];
    __shared__ float sb[32];
    int tid = threadIdx.x;
    for (int i = tid; i < 64 * 32; i += 256) sW[i] = W[i];
    if (tid < 32) sb[tid] = b[tid];
    __syncthreads();
    int lane = tid & 31, wid = tid >> 5;
    int n = blockIdx.x * 8 + wid;
    if (n >= N_NODES) return;
    float xa = x[n * 64 + lane];
    float xb = x[n * 64 + 32 + lane];
    float r = sb[lane];
#pragma unroll
    for (int k = 0; k < 32; k++)
        r = fmaf(__shfl_sync(0xffffffffu, xa, k), sW[k * 32 + lane], r);
#pragma unroll
    for (int k = 0; k < 32; k++)
        r = fmaf(__shfl_sync(0xffffffffu, xb, k), sW[(k + 32) * 32 + lane], r);
    hout[n * 32 + lane] = fmaxf(r, 0.f);
}

// ---------------- w2 repack to bf16 B^T: g_w2tb[col][h] ---------------------
// col = o*32 + k  (k<32): w2[k][h*32+o];  col = 1024+o: b2[h*32+o]
__global__ __launch_bounds__(256) void w2tb_kernel(
    const float* __restrict__ w2, const float* __restrict__ b2) {
    int idx = blockIdx.x * 256 + threadIdx.x;  // 33792 total
    int col = idx >> 5, hh = idx & 31;
    float v;
    if (col < 1024) {
        int o = col >> 5, k = col & 31;
        v = w2[k * 1024 + hh * 32 + o];
    } else {
        int o = col - 1024;
        v = b2[hh * 32 + o];
    }
    __nv_bfloat16 bv = __float2bfloat16(v);
    g_w2tb[col * 32 + hh] = *reinterpret_cast<unsigned short*>(&bv);
}

// ---------------- Y via mma.sync bf16 HMMA ----------------------------------
// C[50048 x 1056] = A(h, bf16)[*,32] @ B(w2tb^T)[32,1056].
// Block: 128 rows x 264 cols. Warp w = m-tile w (16 rows), loops 33 n8-tiles.
__device__ __forceinline__ void hmma16816(float* c, uint32_t a0, uint32_t a1,
                                          uint32_t a2, uint32_t a3,
                                          uint32_t b0, uint32_t b1) {
    asm volatile(
        "mma.sync.aligned.m16n8k16.row.col.f32.bf16.bf16.f32 "
        "{%0,%1,%2,%3}, {%4,%5,%6,%7}, {%8,%9}, {%0,%1,%2,%3};"
        : "+f"(c[0]), "+f"(c[1]), "+f"(c[2]), "+f"(c[3])
        : "r"(a0), "r"(a1), "r"(a2), "r"(a3), "r"(b0), "r"(b1));
}

#define ASTR 36
#define BSTR 36

__global__ __launch_bounds__(256) void y_hmma_kernel(const float* __restrict__ h) {
    __shared__ __nv_bfloat16 sA[128 * ASTR];
    __shared__ __nv_bfloat16 sB[264 * BSTR];
    int tid = threadIdx.x, lane = tid & 31, wid = tid >> 5;
    int m0 = blockIdx.x * 128;
    int nb0 = blockIdx.y * 264;

    // stage A (h -> bf16), rows 128 x 32
    for (int idx = tid; idx < 128 * 32; idx += 256) {
        int r = idx >> 5, k = idx & 31;
        int n = m0 + r;
        float v = (n < N_NODES) ? __ldg(h + (size_t)n * 32 + k) : 0.f;
        sA[r * ASTR + k] = __float2bfloat16(v);
    }
    // stage B slice, 264 x 32 (bf16 already)
    for (int idx = tid; idx < 264 * 32; idx += 256) {
        int r = idx >> 5, k = idx & 31;
        unsigned short us = g_w2tb[(nb0 + r) * 32 + k];
        sB[r * BSTR + k] = *reinterpret_cast<__nv_bfloat16*>(&us);
    }
    __syncthreads();

    // A fragments for this warp's 16 rows (K=32 -> 2 chunks)
    int r = wid * 16 + (lane >> 2);
    int kc = (lane & 3) * 2;
    uint32_t A0[2], A1[2], A2[2], A3[2];
#pragma unroll
    for (int ch = 0; ch < 2; ch++) {
        int kb = ch * 16 + kc;
        A0[ch] = *reinterpret_cast<const uint32_t*>(sA + r * ASTR + kb);
        A1[ch] = *reinterpret_cast<const uint32_t*>(sA + (r + 8) * ASTR + kb);
        A2[ch] = *reinterpret_cast<const uint32_t*>(sA + r * ASTR + kb + 8);
        A3[ch] = *reinterpret_cast<const uint32_t*>(sA + (r + 8) * ASTR + kb + 8);
    }

    int n_row0 = m0 + r;        // C rows for c[0],c[1]
    int n_row1 = n_row0 + 8;    // rows for c[2],c[3]
    int nloc_base = lane >> 2;  // B fragment n within tile

    for (int t = 0; t < 33; t++) {
        int nloc = t * 8 + nloc_base;
        float c[4] = {0.f, 0.f, 0.f, 0.f};
#pragma unroll
        for (int ch = 0; ch < 2; ch++) {
            int kb = ch * 16 + kc;
            uint32_t b0 = *reinterpret_cast<const uint32_t*>(sB + nloc * BSTR + kb);
            uint32_t b1 = *reinterpret_cast<const uint32_t*>(sB + nloc * BSTR + kb + 8);
            hmma16816(c, A0[ch], A1[ch], A2[ch], A3[ch], b0, b1);
        }
        int col = nb0 + t * 8 + kc;   // this thread's first C column
        if (col < 1024) {
            int o = col >> 5, kk = col & 31;
            __nv_bfloat162 p0 = __floats2bfloat162_rn(c[0], c[1]);
            __nv_bfloat162 p1 = __floats2bfloat162_rn(c[2], c[3]);
            if (n_row0 < N_NODES)
                g_Yt[(size_t)n_row0 * 512 + o * 16 + (kk >> 1)] =
                    *reinterpret_cast<unsigned*>(&p0);
            if (n_row1 < N_NODES)
                g_Yt[(size_t)n_row1 * 512 + o * 16 + (kk >> 1)] =
                    *reinterpret_cast<unsigned*>(&p1);
        } else {
            int o = col - 1024;
            if (n_row0 < N_NODES)
                *reinterpret_cast<float2*>(g_Yb + (size_t)n_row0 * 32 + o) =
                    make_float2(c[0], c[1]);
            if (n_row1 < N_NODES)
                *reinterpret_cast<float2*>(g_Yb + (size_t)n_row1 * 32 + o) =
                    make_float2(c[2], c[3]);
        }
    }
}

// ---------------- edge kernel: warp per edge, bf16 Y gather -----------------
__global__ __launch_bounds__(256) void edge_kernel(
    const float* __restrict__ ea, const float* __restrict__ w1,
    const float* __restrict__ b1, float* __restrict__ agg) {
    __shared__ float sw1[16 * 32];
    __shared__ float sb1[32];
    int tid = threadIdx.x, lane = tid & 31, wid = tid >> 5;
    for (int i = tid; i < 512; i += 256) sw1[i] = w1[i];
    if (tid < 32) sb1[tid] = b1[tid];
    __syncthreads();

    int e = blockIdx.x * 8 + wid;
    if (e >= N_EDGES) return;
    int s = g_src[e];
    int d = g_dst[e];

    const float4* eap = reinterpret_cast<const float4*>(ea + (size_t)e * 16);
    float acc = sb1[lane];
#pragma unroll
    for (int j = 0; j < 4; j++) {
        float4 av = __ldg(eap + j);
        acc = fmaf(av.x, sw1[(4 * j + 0) * 32 + lane], acc);
        acc = fmaf(av.y, sw1[(4 * j + 1) * 32 + lane], acc);
        acc = fmaf(av.z, sw1[(4 * j + 2) * 32 + lane], acc);
        acc = fmaf(av.w, sw1[(4 * j + 3) * 32 + lane], acc);
    }
    float he = fmaxf(acc, 0.f);

    float m0 = __ldg(g_Yb + (size_t)s * 32 + lane);
    float m1 = 0.f;
    const uint4* yp = reinterpret_cast<const uint4*>(g_Yt) + (size_t)s * 128 + lane * 4;
#pragma unroll
    for (int i = 0; i < 4; i++) {
        uint4 q = __ldg(yp + i);
        unsigned uu[4] = {q.x, q.y, q.z, q.w};
#pragma unroll
        for (int c = 0; c < 4; c++) {
            int k = i * 8 + c * 2;
            float lo = __int_as_float(uu[c] << 16);
            float hi = __int_as_float(uu[c] & 0xffff0000u);
            m0 = fmaf(__shfl_sync(0xffffffffu, he, k), lo, m0);
            m1 = fmaf(__shfl_sync(0xffffffffu, he, k + 1), hi, m1);
        }
    }
    atomicAdd(&agg[(size_t)d * 32 + lane], m0 + m1);
}

// ---------------- node update: h' = relu(agg/cnt + h@rootW + rootb) ---------
__global__ __launch_bounds__(256) void node_update_kernel(
    const float* __restrict__ hin, const float* __restrict__ agg,
    const float* __restrict__ cnt, const float* __restrict__ rW,
    const float* __restrict__ rb, float* __restrict__ hout) {
    __shared__ float sW[32 * 32];
    __shared__ float sb[32];
    int tid = threadIdx.x;
    for (int i = tid; i < 1024; i += 256) sW[i] = rW[i];
    if (tid < 32) sb[tid] = rb[tid];
    __syncthreads();
    int lane = tid & 31, wid = tid >> 5;
    int n = blockIdx.x * 8 + wid;
    if (n >= N_NODES) return;
    float a = agg[n * 32 + lane] / fmaxf(cnt[n], 1.f);
    float hv = hin[n * 32 + lane];
    float r = sb[lane] + a;
#pragma unroll
    for (int k = 0; k < 32; k++)
        r = fmaf(__shfl_sync(0xffffffffu, hv, k), sW[k * 32 + lane], r);
    hout[n * 32 + lane] = fmaxf(r, 0.f);
}

// ---------------- fused head: z=h@Wo+bo; d1=relu(z@W1+b1); out=d1@W2+b2 -----
__global__ __launch_bounds__(256) void decoder_kernel(
    const float* __restrict__ h, const float* __restrict__ Wo,
    const float* __restrict__ bo, const float* __restrict__ W1,
    const float* __restrict__ b1, const float* __restrict__ W2,
    const float* __restrict__ b2, float* __restrict__ out) {
    __shared__ float sWo[32 * 16], sW1[16 * 32], sW2[32 * 64];
    __shared__ float sbo[16], sb1[32], sb2[64];
    int tid = threadIdx.x;
    for (int i = tid; i < 512; i += 256) { sWo[i] = Wo[i]; sW1[i] = W1[i]; }
    for (int i = tid; i < 2048; i += 256) sW2[i] = W2[i];
    if (tid < 16) sbo[tid] = bo[tid];
    if (tid < 32) sb1[tid] = b1[tid];
    if (tid < 64) sb2[tid] = b2[tid];
    __syncthreads();
    int lane = tid & 31, wid = tid >> 5;
    int n = blockIdx.x * 8 + wid;
    if (n >= N_NODES) return;
    float hv = h[n * 32 + lane];
    int l16 = lane & 15;
    float z = sbo[l16];
#pragma unroll
    for (int k = 0; k < 32; k++)
        z = fmaf(__shfl_sync(0xffffffffu, hv, k), sWo[k * 16 + l16], z);
    float d1 = sb1[lane];
#pragma unroll
    for (int j = 0; j < 16; j++)
        d1 = fmaf(__shfl_sync(0xffffffffu, z, j), sW1[j * 32 + lane], d1);
    d1 = fmaxf(d1, 0.f);
    float o0 = sb2[lane], o1 = sb2[32 + lane];
#pragma unroll
    for (int j = 0; j < 32; j++) {
        float dj = __shfl_sync(0xffffffffu, d1, j);
        o0 = fmaf(dj, sW2[j * 64 + lane], o0);
        o1 = fmaf(dj, sW2[j * 64 + 32 + lane], o1);
    }
    out[n * 64 + lane] = o0;
    out[n * 64 + 32 + lane] = o1;
}

// ---------------- launch ----------------
extern "C" void kernel_launch(void* const* d_in, const int* in_sizes, int n_in,
                              void* d_out, int out_size) {
    const float* x        = (const float*)d_in[0];
    const void*  ei       = d_in[1];
    const float* ea       = (const float*)d_in[2];
    const float* lin_in_w = (const float*)d_in[3];
    const float* lin_in_b = (const float*)d_in[4];
    const float* edge_w1  = (const float*)d_in[5];
    const float* edge_b1  = (const float*)d_in[6];
    const float* edge_w2  = (const float*)d_in[7];
    const float* edge_b2  = (const float*)d_in[8];
    const float* root_w   = (const float*)d_in[9];
    const float* root_b   = (const float*)d_in[10];
    const float* lout_w   = (const float*)d_in[11];
    const float* lout_b   = (const float*)d_in[12];
    const float* dec_w1   = (const float*)d_in[13];
    const float* dec_b1   = (const float*)d_in[14];
    const float* dec_w2   = (const float*)d_in[15];
    const float* dec_b2   = (const float*)d_in[16];
    float* out = (float*)d_out;

    void *p_agg, *p_cnt, *p_hA, *p_hB;
    cudaGetSymbolAddress(&p_agg, g_agg);
    cudaGetSymbolAddress(&p_cnt, g_cnt);
    cudaGetSymbolAddress(&p_hA, g_hA);
    cudaGetSymbolAddress(&p_hB, g_hB);
    float* hbuf[4] = {(float*)p_hA, (float*)p_hB, (float*)p_hA, (float*)p_hB};

    const int EB = (N_EDGES + 255) / 256;
    detect_kernel<<<1, 256>>>(ei);
    normalize_edges<<<EB, 256>>>(ei);
    cudaMemsetAsync(p_cnt, 0, (size_t)N_NODES * sizeof(float), 0);
    count_dst_kernel<<<EB, 256>>>();

    const int NB = (N_NODES + 7) / 8;
    inproj_kernel<<<NB, 256>>>(x, lin_in_w, lin_in_b, (float*)p_hA);

    const int EGB = (N_EDGES + 7) / 8;
    dim3 ygrid(M_TILES, 4);
    for (int L = 0; L < 3; L++) {
        const float* w1 = edge_w1 + L * 16 * 32;
        const float* b1 = edge_b1 + L * 32;
        const float* w2 = edge_w2 + L * 32 * 1024;
        const float* b2 = edge_b2 + L * 1024;
        const float* rw = root_w + L * 32 * 32;
        const float* rb = root_b + L * 32;
        const float* hin = hbuf[L];
        float* hout = hbuf[L + 1];

        w2tb_kernel<<<132, 256>>>(w2, b2);
        y_hmma_kernel<<<ygrid, 256>>>(hin);
        cudaMemsetAsync(p_agg, 0, (size_t)N_NODES * HID * sizeof(float), 0);
        edge_kernel<<<EGB, 256>>>(ea, w1, b1, (float*)p_agg);
        node_update_kernel<<<NB, 256>>>(hin, (const float*)p_agg,
                                        (const float*)p_cnt, rw, rb, hout);
    }
    decoder_kernel<<<NB, 256>>>(hbuf[3], lout_w, lout_b, dec_w1, dec_b1,
                                dec_w2, dec_b2, out);
}